// round 4
// baseline (speedup 1.0000x reference)
#include <cuda_runtime.h>

// Problem constants (fixed by the reference):
// B=16, W=256, S=512, F=768, L=4, E=256, V=50000
#define BB 16
#define WW 256
#define SS 512
#define LL 4
#define NW (WW - 1)

// float4 strides inside layers[L, B, S, F/4=192]
#define LSTRIDE (BB * SS * 192)   // 1,572,864
#define BSTRIDE (SS * 192)        //    98,304

// Generic (slow) path: arbitrary span length. Only used when a word's span is
// not the dataset's universal len==2 (or w==0 handled by caller).
__device__ __noinline__ float4 span_mix_generic(
    const float4* __restrict__ layers4, int b, int ss, int se, int t,
    float w0, float w1, float w2, float w3, float g)
{
    float4 acc = make_float4(0.f, 0.f, 0.f, 0.f);
    const int len = se - ss;
    if (len <= 0) return acc;
    for (int s = ss; s < se; s++) {
        const float4* p = layers4 + (size_t)b * BSTRIDE + (size_t)s * 192 + t;
        float4 v0 = p[0 * LSTRIDE];
        float4 v1 = p[1 * LSTRIDE];
        float4 v2 = p[2 * LSTRIDE];
        float4 v3 = p[3 * LSTRIDE];
        acc.x += w0*v0.x + w1*v1.x + w2*v2.x + w3*v3.x;
        acc.y += w0*v0.y + w1*v1.y + w2*v2.y + w3*v3.y;
        acc.z += w0*v0.z + w1*v1.z + w2*v2.z + w3*v3.z;
        acc.w += w0*v0.w + w1*v1.w + w2*v2.w + w3*v3.w;
    }
    const float sc = g / (float)len;
    acc.x *= sc; acc.y *= sc; acc.z *= sc; acc.w *= sc;
    return acc;
}

// Grid: one block per PAIR of consecutive words = 2048 blocks, 192 threads.
// Per-CTA: 6 scalar index loads (one latency), then 16 front-batched LDG.128s
// streaming 48KB of layers, plus 2 embedding-row float4s on threads 0..63.
// Doubling words-per-CTA amortizes the serial index round-trip and CTA churn.
__global__ __launch_bounds__(192, 3)
void bert_lexer_fused(
    const int* __restrict__ word_indices,   // [B, W]
    const int* __restrict__ span_starts,    // [B, W-1]
    const int* __restrict__ span_ends,      // [B, W-1]
    const float4* __restrict__ emb4,        // [V, E/4=64]
    const float4* __restrict__ layers4,     // [L, B, S, F/4=192]
    const float* __restrict__ layer_weights,// [L]
    const float* __restrict__ gamma,        // [1]
    float4* __restrict__ out4)              // [B, W, (E+F)/4=256]
{
    const int bw0 = blockIdx.x << 1;   // first word of the pair
    const int b   = bw0 >> 8;          // W = 256; pair never straddles batches
    const int w0  = bw0 & (WW - 1);    // w1 = w0 + 1 (>= 1 always)
    const int t   = threadIdx.x;       // 0..191 -> float4 index within F

    // ---- scalar index prologue: all independent, one memory latency ----
    const int idx0  = __ldg(word_indices + bw0);
    const int idx1  = __ldg(word_indices + bw0 + 1);
    const int sbase = b * NW + w0;     // word1's span slot; word0's is sbase-1
    const int ss1   = __ldg(span_starts + sbase);
    const int se1   = __ldg(span_ends   + sbase);
    int ss0 = 0, se0 = 0;
    if (w0 > 0) {
        ss0 = __ldg(span_starts + sbase - 1);
        se0 = __ldg(span_ends   + sbase - 1);
    }

    // ---- softmax over 4 layer weights (overlaps index-load latency) ----
    const float lw0 = __ldg(layer_weights + 0), lw1 = __ldg(layer_weights + 1);
    const float lw2 = __ldg(layer_weights + 2), lw3 = __ldg(layer_weights + 3);
    const float g   = __ldg(gamma);
    const float mx  = fmaxf(fmaxf(lw0, lw1), fmaxf(lw2, lw3));
    const float e0  = __expf(lw0 - mx), e1 = __expf(lw1 - mx);
    const float e2  = __expf(lw2 - mx), e3 = __expf(lw3 - mx);
    const float inv = 1.0f / (e0 + e1 + e2 + e3);
    const float sw0 = e0 * inv, sw1 = e1 * inv, sw2 = e2 * inv, sw3 = e3 * inv;

    // ---- embedding gathers for both words (threads 0..63) ----
    float4 ev0 = make_float4(0.f, 0.f, 0.f, 0.f), ev1 = ev0;
    const bool do_emb = (t < 64);
    if (do_emb) {
        ev0 = emb4[(size_t)idx0 * 64 + t];
        ev1 = emb4[(size_t)idx1 * 64 + t];
    }

    // ---- bert slices for both words ----
    float4 acc0 = make_float4(0.f, 0.f, 0.f, 0.f), acc1 = acc0;
    const bool f0 = (w0 > 0) && (se0 - ss0 == 2);
    const bool f1 = (se1 - ss1 == 2);
    if (f0 && f1) {
        // Fast path: 16 LDG.128s front-batched, nothing between them.
        const float4* p0 = layers4 + (size_t)b * BSTRIDE + (size_t)ss0 * 192 + t;
        const float4* p1 = layers4 + (size_t)b * BSTRIDE + (size_t)ss1 * 192 + t;
        float4 x0 = p0[0*LSTRIDE      ], x1 = p0[0*LSTRIDE + 192];
        float4 x2 = p0[1*LSTRIDE      ], x3 = p0[1*LSTRIDE + 192];
        float4 x4 = p0[2*LSTRIDE      ], x5 = p0[2*LSTRIDE + 192];
        float4 x6 = p0[3*LSTRIDE      ], x7 = p0[3*LSTRIDE + 192];
        float4 y0 = p1[0*LSTRIDE      ], y1 = p1[0*LSTRIDE + 192];
        float4 y2 = p1[1*LSTRIDE      ], y3 = p1[1*LSTRIDE + 192];
        float4 y4 = p1[2*LSTRIDE      ], y5 = p1[2*LSTRIDE + 192];
        float4 y6 = p1[3*LSTRIDE      ], y7 = p1[3*LSTRIDE + 192];

        const float sc = g * 0.5f;                 // / len(=2)
        const float h0 = sw0 * sc, h1 = sw1 * sc, h2 = sw2 * sc, h3 = sw3 * sc;

        acc0.x = h0*(x0.x+x1.x) + h1*(x2.x+x3.x) + h2*(x4.x+x5.x) + h3*(x6.x+x7.x);
        acc0.y = h0*(x0.y+x1.y) + h1*(x2.y+x3.y) + h2*(x4.y+x5.y) + h3*(x6.y+x7.y);
        acc0.z = h0*(x0.z+x1.z) + h1*(x2.z+x3.z) + h2*(x4.z+x5.z) + h3*(x6.z+x7.z);
        acc0.w = h0*(x0.w+x1.w) + h1*(x2.w+x3.w) + h2*(x4.w+x5.w) + h3*(x6.w+x7.w);

        acc1.x = h0*(y0.x+y1.x) + h1*(y2.x+y3.x) + h2*(y4.x+y5.x) + h3*(y6.x+y7.x);
        acc1.y = h0*(y0.y+y1.y) + h1*(y2.y+y3.y) + h2*(y4.y+y5.y) + h3*(y6.y+y7.y);
        acc1.z = h0*(y0.z+y1.z) + h1*(y2.z+y3.z) + h2*(y4.z+y5.z) + h3*(y6.z+y7.z);
        acc1.w = h0*(y0.w+y1.w) + h1*(y2.w+y3.w) + h2*(y4.w+y5.w) + h3*(y6.w+y7.w);
    } else {
        // Rare path: w0==0 pairs (16/2048 blocks) or non-len-2 spans.
        if (w0 > 0)
            acc0 = span_mix_generic(layers4, b, ss0, se0, t, sw0, sw1, sw2, sw3, g);
        acc1 = span_mix_generic(layers4, b, ss1, se1, t, sw0, sw1, sw2, sw3, g);
    }

    // ---- stores: two full 4KB output rows, fully coalesced ----
    float4* __restrict__ o0 = out4 + (size_t)bw0 * 256;
    float4* __restrict__ o1 = o0 + 256;
    if (do_emb) { o0[t] = ev0; o1[t] = ev1; }
    o0[64 + t] = acc0;
    o1[64 + t] = acc1;
}

extern "C" void kernel_launch(void* const* d_in, const int* in_sizes, int n_in,
                              void* d_out, int out_size)
{
    const int*    word_indices  = (const int*)   d_in[0];
    const int*    span_starts   = (const int*)   d_in[1];
    const int*    span_ends     = (const int*)   d_in[2];
    const float4* emb4          = (const float4*)d_in[3];
    const float4* layers4       = (const float4*)d_in[4];
    const float*  layer_weights = (const float*) d_in[5];
    const float*  gamma         = (const float*) d_in[6];
    float4*       out4          = (float4*)      d_out;

    (void)in_sizes; (void)n_in; (void)out_size;

    bert_lexer_fused<<<(BB * WW) / 2, 192>>>(word_indices, span_starts, span_ends,
                                             emb4, layers4, layer_weights, gamma, out4);
}